// round 5
// baseline (speedup 1.0000x reference)
#include <cuda_runtime.h>

#define N 8192
#define THREADS 256
#define ROWS_PER_BLOCK 8
#define KCHUNK 2048
#define NCHUNK (N / KCHUNK)                 // 4
#define ROWGROUPS (N / ROWS_PER_BLOCK)      // 1024
#define GRID (ROWGROUPS * NCHUNK)           // 4096
#define ITERS (KCHUNK / (32 * 4))           // 16 float4 iters per lane

__device__ float g_part[NCHUNK * N];
__device__ unsigned int g_cnt[ROWGROUPS];   // zero-init; self-resets via atomicInc wrap

__global__ __launch_bounds__(THREADS) void gemv_fused_kernel(
    const float* __restrict__ x,
    const float* __restrict__ y,
    const float* __restrict__ W,
    float* __restrict__ out)
{
    __shared__ float r_s[KCHUNK];  // 8 KB
    __shared__ unsigned int s_last;

    const int tid   = threadIdx.x;
    const int bx    = blockIdx.x;
    const int chunk = bx >> 10;          // bx / ROWGROUPS (chunk-major)
    const int rowg  = bx & (ROWGROUPS - 1);
    const int col0  = chunk * KCHUNK;

    // Stage r-chunk with tanh computed inline (y is L2-hot).
    {
        const float4* ysrc = reinterpret_cast<const float4*>(y + col0);
        float4* rdst = reinterpret_cast<float4*>(r_s);
        #pragma unroll
        for (int i = tid; i < KCHUNK / 4; i += THREADS) {
            float4 v = ysrc[i];
            float4 t;
            t.x = tanhf(v.x); t.y = tanhf(v.y);
            t.z = tanhf(v.z); t.w = tanhf(v.w);
            rdst[i] = t;
        }
    }
    __syncthreads();

    const int warp = tid >> 5;
    const int lane = tid & 31;
    const int row  = rowg * ROWS_PER_BLOCK + warp;

    const float4* __restrict__ Wrow =
        reinterpret_cast<const float4*>(W + (size_t)row * N + col0);
    const float4* rs4 = reinterpret_cast<const float4*>(r_s);

    float a0 = 0.f, a1 = 0.f, a2 = 0.f, a3 = 0.f;
    #pragma unroll
    for (int i = 0; i < ITERS; i += 4) {
        float4 w0 = Wrow[(i + 0) * 32 + lane];
        float4 w1 = Wrow[(i + 1) * 32 + lane];
        float4 w2 = Wrow[(i + 2) * 32 + lane];
        float4 w3 = Wrow[(i + 3) * 32 + lane];
        float4 v0 = rs4[(i + 0) * 32 + lane];
        float4 v1 = rs4[(i + 1) * 32 + lane];
        float4 v2 = rs4[(i + 2) * 32 + lane];
        float4 v3 = rs4[(i + 3) * 32 + lane];
        a0 += w0.x * v0.x + w0.y * v0.y + w0.z * v0.z + w0.w * v0.w;
        a1 += w1.x * v1.x + w1.y * v1.y + w1.z * v1.z + w1.w * v1.w;
        a2 += w2.x * v2.x + w2.y * v2.y + w2.z * v2.z + w2.w * v2.w;
        a3 += w3.x * v3.x + w3.y * v3.y + w3.z * v3.z + w3.w * v3.w;
    }
    float acc = (a0 + a1) + (a2 + a3);

    #pragma unroll
    for (int off = 16; off > 0; off >>= 1)
        acc += __shfl_xor_sync(0xFFFFFFFFu, acc, off);

    if (lane == 0)
        g_part[chunk * N + row] = acc;

    __syncthreads();   // all 8 partials of this block are issued

    if (tid == 0) {
        __threadfence();   // make partials visible before signaling
        // atomicInc wraps 3 -> 0: self-resetting counter, no memset needed.
        s_last = (atomicInc(&g_cnt[rowg], NCHUNK - 1) == NCHUNK - 1) ? 1u : 0u;
    }
    __syncthreads();

    // Last-arriving chunk-block finalizes this row-group's 8 outputs.
    if (s_last && warp == 0 && lane < ROWS_PER_BLOCK) {
        const int r = rowg * ROWS_PER_BLOCK + lane;
        float sum = __ldcg(&g_part[0 * N + r])
                  + __ldcg(&g_part[1 * N + r])
                  + __ldcg(&g_part[2 * N + r])
                  + __ldcg(&g_part[3 * N + r]);
        const float DT  = 1e-3f;
        const float TAU = 1e-2f;
        float yr = y[r];
        out[r] = yr + DT * ((-yr + sum + x[r]) / TAU);
    }
}

extern "C" void kernel_launch(void* const* d_in, const int* in_sizes, int n_in,
                              void* d_out, int out_size)
{
    const float* x = (const float*)d_in[0];
    const float* y = (const float*)d_in[1];
    const float* W = (const float*)d_in[2];
    float* out = (float*)d_out;

    gemv_fused_kernel<<<GRID, THREADS>>>(x, y, W, out);
}

// round 6
// speedup vs baseline: 1.0410x; 1.0410x over previous
#include <cuda_runtime.h>

#define N 8192
#define THREADS 256
#define ROWS_PER_BLOCK 8
#define KCHUNK 2048
#define NCHUNK (N / KCHUNK)                 // 4
#define ROWGROUPS (N / ROWS_PER_BLOCK)      // 1024
#define GRID (ROWGROUPS * NCHUNK)           // 4096
#define ITERS (KCHUNK / (32 * 4))           // 16 float4 iters per lane

__device__ float g_part[NCHUNK * N];

__global__ __launch_bounds__(THREADS) void gemv_partial_kernel(
    const float* __restrict__ y,
    const float* __restrict__ W)
{
    __shared__ float r_s[KCHUNK];  // 8 KB

    const int tid   = threadIdx.x;
    const int bx    = blockIdx.x;
    const int chunk = bx >> 10;          // bx / ROWGROUPS (chunk-major)
    const int rowg  = bx & (ROWGROUPS - 1);
    const int col0  = chunk * KCHUNK;

    // Stage r-chunk with tanh computed inline (y is L2-hot).
    {
        const float4* ysrc = reinterpret_cast<const float4*>(y + col0);
        float4* rdst = reinterpret_cast<float4*>(r_s);
        #pragma unroll
        for (int i = tid; i < KCHUNK / 4; i += THREADS) {
            float4 v = ysrc[i];
            float4 t;
            t.x = tanhf(v.x); t.y = tanhf(v.y);
            t.z = tanhf(v.z); t.w = tanhf(v.w);
            rdst[i] = t;
        }
    }
    __syncthreads();

    const int warp = tid >> 5;
    const int lane = tid & 31;
    const int row  = rowg * ROWS_PER_BLOCK + warp;

    const float4* __restrict__ Wrow =
        reinterpret_cast<const float4*>(W + (size_t)row * N + col0);
    const float4* rs4 = reinterpret_cast<const float4*>(r_s);

    float a0 = 0.f, a1 = 0.f, a2 = 0.f, a3 = 0.f;
    #pragma unroll
    for (int i = 0; i < ITERS; i += 4) {
        float4 w0 = Wrow[(i + 0) * 32 + lane];
        float4 w1 = Wrow[(i + 1) * 32 + lane];
        float4 w2 = Wrow[(i + 2) * 32 + lane];
        float4 w3 = Wrow[(i + 3) * 32 + lane];
        float4 v0 = rs4[(i + 0) * 32 + lane];
        float4 v1 = rs4[(i + 1) * 32 + lane];
        float4 v2 = rs4[(i + 2) * 32 + lane];
        float4 v3 = rs4[(i + 3) * 32 + lane];
        a0 += w0.x * v0.x + w0.y * v0.y + w0.z * v0.z + w0.w * v0.w;
        a1 += w1.x * v1.x + w1.y * v1.y + w1.z * v1.z + w1.w * v1.w;
        a2 += w2.x * v2.x + w2.y * v2.y + w2.z * v2.z + w2.w * v2.w;
        a3 += w3.x * v3.x + w3.y * v3.y + w3.z * v3.z + w3.w * v3.w;
    }
    float acc = (a0 + a1) + (a2 + a3);

    #pragma unroll
    for (int off = 16; off > 0; off >>= 1)
        acc += __shfl_xor_sync(0xFFFFFFFFu, acc, off);

    if (lane == 0)
        g_part[chunk * N + row] = acc;

    // Allow the dependent epilogue to begin launching as blocks drain.
    cudaTriggerProgrammaticLaunchCompletion();
}

__global__ void epilogue_kernel(
    const float* __restrict__ x,
    const float* __restrict__ y,
    float* __restrict__ out)
{
    int i = blockIdx.x * blockDim.x + threadIdx.x;
    // Prefetch inputs that don't depend on the GEMV.
    float xi = x[i];
    float yi = y[i];

    // Wait for the primary grid's memory to be visible.
    cudaGridDependencySynchronize();

    float acc = g_part[0 * N + i] + g_part[1 * N + i]
              + g_part[2 * N + i] + g_part[3 * N + i];
    const float DT  = 1e-3f;
    const float TAU = 1e-2f;
    out[i] = yi + DT * ((-yi + acc + xi) / TAU);
}

extern "C" void kernel_launch(void* const* d_in, const int* in_sizes, int n_in,
                              void* d_out, int out_size)
{
    const float* x = (const float*)d_in[0];
    const float* y = (const float*)d_in[1];
    const float* W = (const float*)d_in[2];
    float* out = (float*)d_out;

    gemv_partial_kernel<<<GRID, THREADS>>>(y, W);

    cudaLaunchConfig_t cfg = {};
    cfg.gridDim  = dim3(N / THREADS);   // 32
    cfg.blockDim = dim3(THREADS);
    cfg.stream   = 0;
    cudaLaunchAttribute attr[1];
    attr[0].id = cudaLaunchAttributeProgrammaticStreamSerialization;
    attr[0].val.programmaticStreamSerializationAllowed = 1;
    cfg.attrs    = attr;
    cfg.numAttrs = 1;
    cudaLaunchKernelEx(&cfg, epilogue_kernel, x, y, out);
}

// round 7
// speedup vs baseline: 1.0464x; 1.0052x over previous
#include <cuda_runtime.h>

#define N 8192
#define THREADS 256
#define ROWS_PER_BLOCK 8
#define KCHUNK 2048
#define NCHUNK (N / KCHUNK)                 // 4
#define ROWGROUPS (N / ROWS_PER_BLOCK)      // 1024
#define GRID (ROWGROUPS * NCHUNK)           // 4096
#define ITERS (KCHUNK / (32 * 4))           // 16 float4 iters per lane

__device__ float g_part[NCHUNK * N];
__device__ float g_r[N];

__global__ void tanh_kernel(const float* __restrict__ y)
{
    int i = blockIdx.x * blockDim.x + threadIdx.x;
    g_r[i] = tanhf(y[i]);
}

__global__ __launch_bounds__(THREADS) void gemv_partial_kernel(
    const float* __restrict__ W)
{
    __shared__ float r_s[KCHUNK];  // 8 KB

    const int tid   = threadIdx.x;
    const int bx    = blockIdx.x;
    const int chunk = bx >> 10;          // bx / ROWGROUPS (chunk-major)
    const int rowg  = bx & (ROWGROUPS - 1);
    const int col0  = chunk * KCHUNK;

    // Wait for tanh_kernel's g_r writes to be visible (PDL chain).
    cudaGridDependencySynchronize();

    // Stage r-chunk: pure copy, no math (g_r is L2-hot).
    {
        const float4* rsrc = reinterpret_cast<const float4*>(g_r + col0);
        float4* rdst = reinterpret_cast<float4*>(r_s);
        #pragma unroll
        for (int i = tid; i < KCHUNK / 4; i += THREADS)
            rdst[i] = __ldg(&rsrc[i]);
    }
    __syncthreads();

    const int warp = tid >> 5;
    const int lane = tid & 31;
    const int row  = rowg * ROWS_PER_BLOCK + warp;

    const float4* __restrict__ Wrow =
        reinterpret_cast<const float4*>(W + (size_t)row * N + col0);
    const float4* rs4 = reinterpret_cast<const float4*>(r_s);

    float a0 = 0.f, a1 = 0.f, a2 = 0.f, a3 = 0.f;
    #pragma unroll
    for (int i = 0; i < ITERS; i += 4) {
        float4 w0 = Wrow[(i + 0) * 32 + lane];
        float4 w1 = Wrow[(i + 1) * 32 + lane];
        float4 w2 = Wrow[(i + 2) * 32 + lane];
        float4 w3 = Wrow[(i + 3) * 32 + lane];
        float4 v0 = rs4[(i + 0) * 32 + lane];
        float4 v1 = rs4[(i + 1) * 32 + lane];
        float4 v2 = rs4[(i + 2) * 32 + lane];
        float4 v3 = rs4[(i + 3) * 32 + lane];
        a0 += w0.x * v0.x + w0.y * v0.y + w0.z * v0.z + w0.w * v0.w;
        a1 += w1.x * v1.x + w1.y * v1.y + w1.z * v1.z + w1.w * v1.w;
        a2 += w2.x * v2.x + w2.y * v2.y + w2.z * v2.z + w2.w * v2.w;
        a3 += w3.x * v3.x + w3.y * v3.y + w3.z * v3.z + w3.w * v3.w;
    }
    float acc = (a0 + a1) + (a2 + a3);

    #pragma unroll
    for (int off = 16; off > 0; off >>= 1)
        acc += __shfl_xor_sync(0xFFFFFFFFu, acc, off);

    if (lane == 0)
        g_part[chunk * N + row] = acc;
}

__global__ void epilogue_kernel(
    const float* __restrict__ x,
    const float* __restrict__ y,
    float* __restrict__ out)
{
    int i = blockIdx.x * blockDim.x + threadIdx.x;
    float xi = x[i];   // independent of GEMV
    float yi = y[i];

    cudaGridDependencySynchronize();

    float acc = g_part[0 * N + i] + g_part[1 * N + i]
              + g_part[2 * N + i] + g_part[3 * N + i];
    const float DT  = 1e-3f;
    const float TAU = 1e-2f;
    out[i] = yi + DT * ((-yi + acc + xi) / TAU);
}

extern "C" void kernel_launch(void* const* d_in, const int* in_sizes, int n_in,
                              void* d_out, int out_size)
{
    const float* x = (const float*)d_in[0];
    const float* y = (const float*)d_in[1];
    const float* W = (const float*)d_in[2];
    float* out = (float*)d_out;

    tanh_kernel<<<64, 128>>>(y);

    cudaLaunchAttribute attr[1];
    attr[0].id = cudaLaunchAttributeProgrammaticStreamSerialization;
    attr[0].val.programmaticStreamSerializationAllowed = 1;

    cudaLaunchConfig_t cfg1 = {};
    cfg1.gridDim  = dim3(GRID);
    cfg1.blockDim = dim3(THREADS);
    cfg1.stream   = 0;
    cfg1.attrs    = attr;
    cfg1.numAttrs = 1;
    cudaLaunchKernelEx(&cfg1, gemv_partial_kernel, W);

    cudaLaunchConfig_t cfg2 = {};
    cfg2.gridDim  = dim3(N / THREADS);   // 32
    cfg2.blockDim = dim3(THREADS);
    cfg2.stream   = 0;
    cfg2.attrs    = attr;
    cfg2.numAttrs = 1;
    cudaLaunchKernelEx(&cfg2, epilogue_kernel, x, y, out);
}

// round 8
// speedup vs baseline: 1.0573x; 1.0104x over previous
#include <cuda_runtime.h>

#define N 8192
#define THREADS 256
#define ROWS_PER_BLOCK 8
#define KCHUNK 2048
#define NCHUNK (N / KCHUNK)                 // 4
#define ROWGROUPS (N / ROWS_PER_BLOCK)      // 1024
#define GRID (ROWGROUPS * NCHUNK)           // 4096
#define ITERS (KCHUNK / (32 * 4))           // 16 float4 iters per lane

__device__ float g_part[NCHUNK * N];

__device__ __forceinline__ float fast_tanh(float v)
{
    float o;
    asm("tanh.approx.f32 %0, %1;" : "=f"(o) : "f"(v));
    return o;
}

__global__ __launch_bounds__(THREADS) void gemv_partial_kernel(
    const float* __restrict__ y,
    const float* __restrict__ W)
{
    __shared__ float r_s[KCHUNK];  // 8 KB

    const int tid   = threadIdx.x;
    const int bx    = blockIdx.x;
    const int chunk = bx >> 10;          // bx / ROWGROUPS (chunk-major)
    const int rowg  = bx & (ROWGROUPS - 1);
    const int col0  = chunk * KCHUNK;

    // Stage r-chunk: tanh via single-instruction MUFU.TANH (hidden under DRAM).
    {
        const float4* ysrc = reinterpret_cast<const float4*>(y + col0);
        float4* rdst = reinterpret_cast<float4*>(r_s);
        #pragma unroll
        for (int i = tid; i < KCHUNK / 4; i += THREADS) {
            float4 v = ysrc[i];
            float4 t;
            t.x = fast_tanh(v.x); t.y = fast_tanh(v.y);
            t.z = fast_tanh(v.z); t.w = fast_tanh(v.w);
            rdst[i] = t;
        }
    }
    __syncthreads();

    const int warp = tid >> 5;
    const int lane = tid & 31;
    const int row  = rowg * ROWS_PER_BLOCK + warp;

    const float4* __restrict__ Wrow =
        reinterpret_cast<const float4*>(W + (size_t)row * N + col0);
    const float4* rs4 = reinterpret_cast<const float4*>(r_s);

    float a0 = 0.f, a1 = 0.f, a2 = 0.f, a3 = 0.f;
    #pragma unroll
    for (int i = 0; i < ITERS; i += 4) {
        float4 w0 = Wrow[(i + 0) * 32 + lane];
        float4 w1 = Wrow[(i + 1) * 32 + lane];
        float4 w2 = Wrow[(i + 2) * 32 + lane];
        float4 w3 = Wrow[(i + 3) * 32 + lane];
        float4 v0 = rs4[(i + 0) * 32 + lane];
        float4 v1 = rs4[(i + 1) * 32 + lane];
        float4 v2 = rs4[(i + 2) * 32 + lane];
        float4 v3 = rs4[(i + 3) * 32 + lane];
        a0 += w0.x * v0.x + w0.y * v0.y + w0.z * v0.z + w0.w * v0.w;
        a1 += w1.x * v1.x + w1.y * v1.y + w1.z * v1.z + w1.w * v1.w;
        a2 += w2.x * v2.x + w2.y * v2.y + w2.z * v2.z + w2.w * v2.w;
        a3 += w3.x * v3.x + w3.y * v3.y + w3.z * v3.z + w3.w * v3.w;
    }
    float acc = (a0 + a1) + (a2 + a3);

    #pragma unroll
    for (int off = 16; off > 0; off >>= 1)
        acc += __shfl_xor_sync(0xFFFFFFFFu, acc, off);

    if (lane == 0)
        __stcg(&g_part[chunk * N + row], acc);
}

__global__ void epilogue_kernel(
    const float* __restrict__ x,
    const float* __restrict__ y,
    float* __restrict__ out)
{
    int i = blockIdx.x * blockDim.x + threadIdx.x;
    float xi = x[i];   // independent of GEMV
    float yi = y[i];

    cudaGridDependencySynchronize();

    float acc = g_part[0 * N + i] + g_part[1 * N + i]
              + g_part[2 * N + i] + g_part[3 * N + i];
    const float DT  = 1e-3f;
    const float TAU = 1e-2f;
    out[i] = yi + DT * ((-yi + acc + xi) / TAU);
}

extern "C" void kernel_launch(void* const* d_in, const int* in_sizes, int n_in,
                              void* d_out, int out_size)
{
    const float* x = (const float*)d_in[0];
    const float* y = (const float*)d_in[1];
    const float* W = (const float*)d_in[2];
    float* out = (float*)d_out;

    gemv_partial_kernel<<<GRID, THREADS>>>(y, W);

    cudaLaunchConfig_t cfg = {};
    cfg.gridDim  = dim3(N / THREADS);   // 32
    cfg.blockDim = dim3(THREADS);
    cfg.stream   = 0;
    cudaLaunchAttribute attr[1];
    attr[0].id = cudaLaunchAttributeProgrammaticStreamSerialization;
    attr[0].val.programmaticStreamSerializationAllowed = 1;
    cfg.attrs    = attr;
    cfg.numAttrs = 1;
    cudaLaunchKernelEx(&cfg, epilogue_kernel, x, y, out);
}